// round 10
// baseline (speedup 1.0000x reference)
#include <cuda_runtime.h>
#include <cstdint>
#include <cstddef>

#define BB 8
#define NN 4096
#define MM 1024
#define DD 64
#define PTS 16
#define NPAIR (PTS / 2)
#define FPS_THREADS 256   /* NN / PTS */
#define NWARP (FPS_THREADS / 32)
#define P2T 256
#define OUT_COLS 134      /* D + 3 + D + 3 */

// ---------------- scratch (no allocations allowed) ----------------
__device__ int   g_sidx[BB * MM];   // global index of sampled points
__device__ float g_lrx[BB * MM];    // sampled positions, SoA
__device__ float g_lry[BB * MM];
__device__ float g_lrz[BB * MM];

// ---------------- packed f32x2 helpers (bit-exact per-lane .rn ops) ------
__device__ __forceinline__ unsigned long long packf2(float lo, float hi) {
    unsigned long long r;
    asm("mov.b64 %0, {%1, %2};" : "=l"(r) : "f"(lo), "f"(hi));
    return r;
}
__device__ __forceinline__ void unpackf2(unsigned long long v, float& lo, float& hi) {
    asm("mov.b64 {%0, %1}, %2;" : "=f"(lo), "=f"(hi) : "l"(v));
}
__device__ __forceinline__ unsigned long long addx2(unsigned long long a, unsigned long long b) {
    unsigned long long r;
    asm("add.rn.f32x2 %0, %1, %2;" : "=l"(r) : "l"(a), "l"(b));
    return r;
}
__device__ __forceinline__ unsigned long long mulx2(unsigned long long a, unsigned long long b) {
    unsigned long long r;
    asm("mul.rn.f32x2 %0, %1, %2;" : "=l"(r) : "l"(a), "l"(b));
    return r;
}
__device__ __forceinline__ unsigned redux_max_u32(unsigned v) {
    unsigned r;
    asm("redux.sync.max.u32 %0, %1, 0xffffffff;" : "=r"(r) : "r"(v));
    return r;
}
__device__ __forceinline__ unsigned long long maxu64(unsigned long long a, unsigned long long b) {
    return (a > b) ? a : b;
}

struct FpsShared {
    unsigned long long wkey[2][NWARP];   // double-buffered per-warp keys (16B aligned)
    float xs[NN], ys[NN], zs[NN];
};

// ---------------- Kernel 1: farthest point sampling, one CTA per cloud ----------------
__global__ __launch_bounds__(FPS_THREADS, 1)
void fps_kernel(const float* __restrict__ pos) {
    extern __shared__ unsigned char smraw[];
    FpsShared* sm = reinterpret_cast<FpsShared*>(smraw);
    const int b = blockIdx.x;
    const int t = threadIdx.x;
    const int warp = t >> 5;
    const float* posb = pos + (size_t)b * NN * 3;

    for (int i = t; i < NN; i += FPS_THREADS) {
        sm->xs[i] = posb[3 * i + 0];
        sm->ys[i] = posb[3 * i + 1];
        sm->zs[i] = posb[3 * i + 2];
    }
    __syncthreads();

    // Per-thread points, pre-negated and packed in pairs: npx[p] = (-x[2p], -x[2p+1])
    unsigned long long npx[NPAIR], npy[NPAIR], npz[NPAIR];
    float mind[PTS];
    const int base = t * PTS;
#pragma unroll
    for (int p = 0; p < NPAIR; p++) {
        npx[p] = packf2(-sm->xs[base + 2 * p], -sm->xs[base + 2 * p + 1]);
        npy[p] = packf2(-sm->ys[base + 2 * p], -sm->ys[base + 2 * p + 1]);
        npz[p] = packf2(-sm->zs[base + 2 * p], -sm->zs[base + 2 * p + 1]);
    }
#pragma unroll
    for (int j = 0; j < PTS; j++) mind[j] = 3.402823466e+38f;  // finfo(float32).max

    float lx = sm->xs[0], ly = sm->ys[0], lz = sm->zs[0];  // winner of step 0
    if (t == 0) {
        g_sidx[b * MM] = b * NN;
        g_lrx[b * MM] = lx; g_lry[b * MM] = ly; g_lrz[b * MM] = lz;
    }
    const unsigned nbase = ~(unsigned)base;   // ~(base+id) == nbase - id

    for (int step = 1; step < MM; ++step) {
        const unsigned long long lxx = packf2(lx, lx);
        const unsigned long long lyy = packf2(ly, ly);
        const unsigned long long lzz = packf2(lz, lz);

        // Distances via packed math: dx = lx + (-px) == lx - px ; square identical to (px-lx)^2.
#pragma unroll
        for (int p = 0; p < NPAIR; p++) {
            unsigned long long dx = addx2(lxx, npx[p]);
            unsigned long long dy = addx2(lyy, npy[p]);
            unsigned long long dz = addx2(lzz, npz[p]);
            unsigned long long s  = addx2(addx2(mulx2(dx, dx), mulx2(dy, dy)),
                                          mulx2(dz, dz));
            float d0, d1;
            unpackf2(s, d0, d1);
            mind[2 * p]     = fminf(mind[2 * p], d0);
            mind[2 * p + 1] = fminf(mind[2 * p + 1], d1);
        }

        // In-thread argmax tree; level-1 indices are immediates (no 16 MOV + 16 IADD
        // leaf init); lower index wins ties (first-occurrence semantics).
        float v[NPAIR]; int id[NPAIR];
#pragma unroll
        for (int k = 0; k < NPAIR; k++) {
            bool keep = mind[2 * k] >= mind[2 * k + 1];
            v[k]  = keep ? mind[2 * k] : mind[2 * k + 1];
            id[k] = keep ? (2 * k) : (2 * k + 1);
        }
#pragma unroll
        for (int s = 1; s < NPAIR; s <<= 1) {
#pragma unroll
            for (int j = 0; j < NPAIR; j += 2 * s) {
                bool keep = v[j] >= v[j + s];
                v[j]  = keep ? v[j]  : v[j + s];
                id[j] = keep ? id[j] : id[j + s];
            }
        }

        // Warp argmax via two redux: max value bits, then min global index among maxima.
        // (nonnegative floats: bit order == numeric order)
        unsigned vb = __float_as_uint(v[0]);
        unsigned vmax = redux_max_u32(vb);
        unsigned cand = (vb == vmax) ? (nbase - (unsigned)id[0]) : 0u;  // = ~(base+id)
        unsigned imax = redux_max_u32(cand);           // = ~(min idx among max lanes)
        if ((t & 31) == 0)
            sm->wkey[step & 1][warp] =
                ((unsigned long long)vmax << 32) | (unsigned long long)imax;
        __syncthreads();

        // Cross-warp: every thread reduces 8 keys via pairwise max tree,
        // loaded as 4 aligned 16B vectors (shorter dependent chain than serial).
        const ulonglong2* wk2 =
            reinterpret_cast<const ulonglong2*>(sm->wkey[step & 1]);
        ulonglong2 k01 = wk2[0], k23 = wk2[1], k45 = wk2[2], k67 = wk2[3];
        unsigned long long a0 = maxu64(k01.x, k01.y);
        unsigned long long a1 = maxu64(k23.x, k23.y);
        unsigned long long a2 = maxu64(k45.x, k45.y);
        unsigned long long a3 = maxu64(k67.x, k67.y);
        unsigned long long bk = maxu64(maxu64(a0, a1), maxu64(a2, a3));

        unsigned widx = ~((unsigned)bk);
        lx = sm->xs[widx]; ly = sm->ys[widx]; lz = sm->zs[widx];  // broadcast LDS

        if (t == 0) {
            g_sidx[b * MM + step] = b * NN + (int)widx;
            g_lrx[b * MM + step] = lx;
            g_lry[b * MM + step] = ly;
            g_lrz[b * MM + step] = lz;
        }
    }
}

// ---------------- Kernel 2: 1-NN over sampled points + fused output gather ----------------
__global__ __launch_bounds__(P2T)
void knn_out_kernel(const float* __restrict__ x, const float* __restrict__ pos,
                    float* __restrict__ out) {
    __shared__ unsigned long long nlx[MM / 2], nly[MM / 2], nlz[MM / 2];
    __shared__ int gsrc[P2T];

    const int b = blockIdx.y;
    // Load sampled positions, negated + packed in pairs.
    const float2* fx = (const float2*)(g_lrx) + b * (MM / 2);
    const float2* fy = (const float2*)(g_lry) + b * (MM / 2);
    const float2* fz = (const float2*)(g_lrz) + b * (MM / 2);
    for (int i = threadIdx.x; i < MM / 2; i += P2T) {
        float2 a = fx[i]; nlx[i] = packf2(-a.x, -a.y);
        float2 c = fy[i]; nly[i] = packf2(-c.x, -c.y);
        float2 e = fz[i]; nlz[i] = packf2(-e.x, -e.y);
    }
    __syncthreads();

    const int rlocal = blockIdx.x * P2T + threadIdx.x;
    const int row = b * NN + rlocal;
    const float ax = pos[3 * row + 0];
    const float ay = pos[3 * row + 1];
    const float az = pos[3 * row + 2];
    const unsigned long long axx = packf2(ax, ax);
    const unsigned long long ayy = packf2(ay, ay);
    const unsigned long long azz = packf2(az, az);

    // 4 interleaved argmin chains (2 packed pairs per iteration).
    float bv0 = 3.4e+38f, bv1 = 3.4e+38f, bv2 = 3.4e+38f, bv3 = 3.4e+38f;
    int bi0 = 0, bi1 = 1, bi2 = 2, bi3 = 3;
    for (int j = 0; j < MM; j += 4) {
        int p = j >> 1;
        unsigned long long dxA = addx2(axx, nlx[p]);
        unsigned long long dyA = addx2(ayy, nly[p]);
        unsigned long long dzA = addx2(azz, nlz[p]);
        unsigned long long sA  = addx2(addx2(mulx2(dxA, dxA), mulx2(dyA, dyA)),
                                       mulx2(dzA, dzA));
        unsigned long long dxB = addx2(axx, nlx[p + 1]);
        unsigned long long dyB = addx2(ayy, nly[p + 1]);
        unsigned long long dzB = addx2(azz, nlz[p + 1]);
        unsigned long long sB  = addx2(addx2(mulx2(dxB, dxB), mulx2(dyB, dyB)),
                                       mulx2(dzB, dzB));
        float d0, d1, d2, d3;
        unpackf2(sA, d0, d1);
        unpackf2(sB, d2, d3);
        if (d0 < bv0) { bv0 = d0; bi0 = j + 0; }
        if (d1 < bv1) { bv1 = d1; bi1 = j + 1; }
        if (d2 < bv2) { bv2 = d2; bi2 = j + 2; }
        if (d3 < bv3) { bv3 = d3; bi3 = j + 3; }
    }
    // Combine with first-index tie-break (matches jnp.argmin).
    bool t1 = (bv1 < bv0) || (bv1 == bv0 && bi1 < bi0);
    float va = t1 ? bv1 : bv0;  int ia = t1 ? bi1 : bi0;
    bool t2 = (bv3 < bv2) || (bv3 == bv2 && bi3 < bi2);
    float vb = t2 ? bv3 : bv2;  int ib = t2 ? bi3 : bi2;
    bool t3 = (vb < va) || (vb == va && ib < ia);
    int bi = t3 ? ib : ia;

    gsrc[threadIdx.x] = g_sidx[b * MM + bi];
    __syncthreads();

    // Cooperative, fully-coalesced output write: rows [rowbase, rowbase+P2T)
    const long long rowbase = (long long)b * NN + (long long)blockIdx.x * P2T;
    float* outp = out + (size_t)rowbase * OUT_COLS;
    for (int e = threadIdx.x; e < P2T * OUT_COLS; e += P2T) {
        int r = e / OUT_COLS;
        int c = e - r * OUT_COLS;
        int grow = (int)rowbase + r;
        int g = gsrc[r];
        float val;
        if (c < DD)               val = x[(size_t)grow * DD + c];
        else if (c < DD + 3)      val = pos[3 * grow + (c - DD)];
        else if (c < 2 * DD + 3)  val = x[(size_t)g * DD + (c - DD - 3)];
        else                      val = pos[3 * g + (c - 2 * DD - 3)];
        outp[e] = val;
    }
}

// ---------------- Kernel 3: optional batch output (if harness concatenates tuple) ----------
__global__ void batch_kernel(float* __restrict__ out) {
    int i = blockIdx.x * blockDim.x + threadIdx.x;
    if (i < BB * NN) {
        out[(size_t)BB * NN * OUT_COLS + (size_t)BB * NN * 3 + i] = (float)(i >> 12); // i / NN
    }
}

extern "C" void kernel_launch(void* const* d_in, const int* in_sizes, int n_in,
                              void* d_out, int out_size) {
    const float* x   = (const float*)d_in[0];
    const float* pos = (const float*)d_in[1];
    float* out = (float*)d_out;

    cudaFuncSetAttribute(fps_kernel, cudaFuncAttributeMaxDynamicSharedMemorySize,
                         (int)sizeof(FpsShared));
    fps_kernel<<<BB, FPS_THREADS, sizeof(FpsShared)>>>(pos);
    knn_out_kernel<<<dim3(NN / P2T, BB), P2T>>>(x, pos, out);

    const long long outx = (long long)BB * NN * OUT_COLS;            // 4390912
    const long long zs   = (long long)BB * NN * 3;                   // 98304
    if ((long long)out_size >= outx + zs) {
        cudaMemsetAsync(out + outx, 0, (size_t)zs * sizeof(float));
    }
    if ((long long)out_size >= outx + zs + (long long)BB * NN) {
        batch_kernel<<<(BB * NN + 255) / 256, 256>>>(out);
    }
}

// round 11
// speedup vs baseline: 1.0511x; 1.0511x over previous
#include <cuda_runtime.h>
#include <cstdint>
#include <cstddef>

#define BB 8
#define NN 4096
#define MM 1024
#define DD 64
#define PTS 16
#define NPAIR (PTS / 2)
#define FPS_THREADS 256   /* NN / PTS */
#define NWARP (FPS_THREADS / 32)
#define P2T 128           /* knn threads per block (halved for 2 blocks/SM) */
#define OUT_COLS 134      /* D + 3 + D + 3 */

// ---------------- scratch (no allocations allowed) ----------------
__device__ int   g_sidx[BB * MM];   // global index of sampled points
__device__ float g_lrx[BB * MM];    // sampled positions, SoA
__device__ float g_lry[BB * MM];
__device__ float g_lrz[BB * MM];

// ---------------- packed f32x2 helpers (bit-exact per-lane .rn ops) ------
__device__ __forceinline__ unsigned long long packf2(float lo, float hi) {
    unsigned long long r;
    asm("mov.b64 %0, {%1, %2};" : "=l"(r) : "f"(lo), "f"(hi));
    return r;
}
__device__ __forceinline__ void unpackf2(unsigned long long v, float& lo, float& hi) {
    asm("mov.b64 {%0, %1}, %2;" : "=f"(lo), "=f"(hi) : "l"(v));
}
__device__ __forceinline__ unsigned long long addx2(unsigned long long a, unsigned long long b) {
    unsigned long long r;
    asm("add.rn.f32x2 %0, %1, %2;" : "=l"(r) : "l"(a), "l"(b));
    return r;
}
__device__ __forceinline__ unsigned long long mulx2(unsigned long long a, unsigned long long b) {
    unsigned long long r;
    asm("mul.rn.f32x2 %0, %1, %2;" : "=l"(r) : "l"(a), "l"(b));
    return r;
}
__device__ __forceinline__ unsigned redux_max_u32(unsigned v) {
    unsigned r;
    asm("redux.sync.max.u32 %0, %1, 0xffffffff;" : "=r"(r) : "r"(v));
    return r;
}

struct FpsShared {
    unsigned long long wkey[2][NWARP];   // double-buffered per-warp keys
    float xs[NN], ys[NN], zs[NN];
};

// ---------------- Kernel 1: farthest point sampling, one CTA per cloud ----------------
// (byte-identical to the validated 377us configuration — do not modify)
__global__ __launch_bounds__(FPS_THREADS, 1)
void fps_kernel(const float* __restrict__ pos) {
    extern __shared__ unsigned char smraw[];
    FpsShared* sm = reinterpret_cast<FpsShared*>(smraw);
    const int b = blockIdx.x;
    const int t = threadIdx.x;
    const int warp = t >> 5;
    const float* posb = pos + (size_t)b * NN * 3;

    for (int i = t; i < NN; i += FPS_THREADS) {
        sm->xs[i] = posb[3 * i + 0];
        sm->ys[i] = posb[3 * i + 1];
        sm->zs[i] = posb[3 * i + 2];
    }
    __syncthreads();

    // Per-thread points, pre-negated and packed in pairs: npx[p] = (-x[2p], -x[2p+1])
    unsigned long long npx[NPAIR], npy[NPAIR], npz[NPAIR];
    float mind[PTS];
    const int base = t * PTS;
#pragma unroll
    for (int p = 0; p < NPAIR; p++) {
        npx[p] = packf2(-sm->xs[base + 2 * p], -sm->xs[base + 2 * p + 1]);
        npy[p] = packf2(-sm->ys[base + 2 * p], -sm->ys[base + 2 * p + 1]);
        npz[p] = packf2(-sm->zs[base + 2 * p], -sm->zs[base + 2 * p + 1]);
    }
#pragma unroll
    for (int j = 0; j < PTS; j++) mind[j] = 3.402823466e+38f;  // finfo(float32).max

    float lx = sm->xs[0], ly = sm->ys[0], lz = sm->zs[0];  // winner of step 0
    if (t == 0) {
        g_sidx[b * MM] = b * NN;
        g_lrx[b * MM] = lx; g_lry[b * MM] = ly; g_lrz[b * MM] = lz;
    }

    for (int step = 1; step < MM; ++step) {
        const unsigned long long lxx = packf2(lx, lx);
        const unsigned long long lyy = packf2(ly, ly);
        const unsigned long long lzz = packf2(lz, lz);

        // Distances via packed math: dx = lx + (-px) == lx - px ; square identical to (px-lx)^2.
#pragma unroll
        for (int p = 0; p < NPAIR; p++) {
            unsigned long long dx = addx2(lxx, npx[p]);
            unsigned long long dy = addx2(lyy, npy[p]);
            unsigned long long dz = addx2(lzz, npz[p]);
            unsigned long long s  = addx2(addx2(mulx2(dx, dx), mulx2(dy, dy)),
                                          mulx2(dz, dz));
            float d0, d1;
            unpackf2(s, d0, d1);
            mind[2 * p]     = fminf(mind[2 * p], d0);
            mind[2 * p + 1] = fminf(mind[2 * p + 1], d1);
        }

        // In-thread argmax tree; lower index wins ties (first-occurrence semantics).
        float v[PTS]; int id[PTS];
#pragma unroll
        for (int j = 0; j < PTS; j++) { v[j] = mind[j]; id[j] = base + j; }
#pragma unroll
        for (int s = 1; s < PTS; s <<= 1) {
#pragma unroll
            for (int j = 0; j < PTS; j += 2 * s) {
                bool keep = v[j] >= v[j + s];
                v[j]  = keep ? v[j]  : v[j + s];
                id[j] = keep ? id[j] : id[j + s];
            }
        }

        // Warp argmax via two redux: max value bits, then min index among maxima.
        // (nonnegative floats: bit order == numeric order)
        unsigned vb = __float_as_uint(v[0]);
        unsigned vmax = redux_max_u32(vb);
        unsigned cand = (vb == vmax) ? ~(unsigned)id[0] : 0u;
        unsigned imax = redux_max_u32(cand);           // = ~(min idx among max lanes)
        if ((t & 31) == 0)
            sm->wkey[step & 1][warp] =
                ((unsigned long long)vmax << 32) | (unsigned long long)imax;
        __syncthreads();

        // Every thread reduces the NWARP keys redundantly (no second barrier).
        const unsigned long long* wk = sm->wkey[step & 1];
        unsigned long long bk = wk[0];
#pragma unroll
        for (int w = 1; w < NWARP; w++) {
            unsigned long long k = wk[w];
            if (k > bk) bk = k;   // equal keys impossible (idx embedded)
        }
        unsigned widx = ~((unsigned)bk);
        lx = sm->xs[widx]; ly = sm->ys[widx]; lz = sm->zs[widx];  // broadcast LDS

        if (t == 0) {
            g_sidx[b * MM + step] = b * NN + (int)widx;
            g_lrx[b * MM + step] = lx;
            g_lry[b * MM + step] = ly;
            g_lrz[b * MM + step] = lz;
        }
    }
}

// ---------------- Kernel 2: 1-NN over sampled points + fused output gather ----------------
// Same per-thread algorithm as the validated version; 128 threads/block and 2x grid
// so ~2 blocks land per SM (better latency hiding for the LDS-bound distance loop).
__global__ __launch_bounds__(P2T)
void knn_out_kernel(const float* __restrict__ x, const float* __restrict__ pos,
                    float* __restrict__ out) {
    __shared__ unsigned long long nlx[MM / 2], nly[MM / 2], nlz[MM / 2];
    __shared__ int gsrc[P2T];

    const int b = blockIdx.y;
    // Load sampled positions, negated + packed in pairs.
    const float2* fx = (const float2*)(g_lrx) + b * (MM / 2);
    const float2* fy = (const float2*)(g_lry) + b * (MM / 2);
    const float2* fz = (const float2*)(g_lrz) + b * (MM / 2);
    for (int i = threadIdx.x; i < MM / 2; i += P2T) {
        float2 a = fx[i]; nlx[i] = packf2(-a.x, -a.y);
        float2 c = fy[i]; nly[i] = packf2(-c.x, -c.y);
        float2 e = fz[i]; nlz[i] = packf2(-e.x, -e.y);
    }
    __syncthreads();

    const int rlocal = blockIdx.x * P2T + threadIdx.x;
    const int row = b * NN + rlocal;
    const float ax = pos[3 * row + 0];
    const float ay = pos[3 * row + 1];
    const float az = pos[3 * row + 2];
    const unsigned long long axx = packf2(ax, ax);
    const unsigned long long ayy = packf2(ay, ay);
    const unsigned long long azz = packf2(az, az);

    // 4 interleaved argmin chains (2 packed pairs per iteration).
    float bv0 = 3.4e+38f, bv1 = 3.4e+38f, bv2 = 3.4e+38f, bv3 = 3.4e+38f;
    int bi0 = 0, bi1 = 1, bi2 = 2, bi3 = 3;
    for (int j = 0; j < MM; j += 4) {
        int p = j >> 1;
        unsigned long long dxA = addx2(axx, nlx[p]);
        unsigned long long dyA = addx2(ayy, nly[p]);
        unsigned long long dzA = addx2(azz, nlz[p]);
        unsigned long long sA  = addx2(addx2(mulx2(dxA, dxA), mulx2(dyA, dyA)),
                                       mulx2(dzA, dzA));
        unsigned long long dxB = addx2(axx, nlx[p + 1]);
        unsigned long long dyB = addx2(ayy, nly[p + 1]);
        unsigned long long dzB = addx2(azz, nlz[p + 1]);
        unsigned long long sB  = addx2(addx2(mulx2(dxB, dxB), mulx2(dyB, dyB)),
                                       mulx2(dzB, dzB));
        float d0, d1, d2, d3;
        unpackf2(sA, d0, d1);
        unpackf2(sB, d2, d3);
        if (d0 < bv0) { bv0 = d0; bi0 = j + 0; }
        if (d1 < bv1) { bv1 = d1; bi1 = j + 1; }
        if (d2 < bv2) { bv2 = d2; bi2 = j + 2; }
        if (d3 < bv3) { bv3 = d3; bi3 = j + 3; }
    }
    // Combine with first-index tie-break (matches jnp.argmin).
    bool t1 = (bv1 < bv0) || (bv1 == bv0 && bi1 < bi0);
    float va = t1 ? bv1 : bv0;  int ia = t1 ? bi1 : bi0;
    bool t2 = (bv3 < bv2) || (bv3 == bv2 && bi3 < bi2);
    float vb = t2 ? bv3 : bv2;  int ib = t2 ? bi3 : bi2;
    bool t3 = (vb < va) || (vb == va && ib < ia);
    int bi = t3 ? ib : ia;

    gsrc[threadIdx.x] = g_sidx[b * MM + bi];
    __syncthreads();

    // Cooperative, fully-coalesced output write: rows [rowbase, rowbase+P2T)
    const long long rowbase = (long long)b * NN + (long long)blockIdx.x * P2T;
    float* outp = out + (size_t)rowbase * OUT_COLS;
    for (int e = threadIdx.x; e < P2T * OUT_COLS; e += P2T) {
        int r = e / OUT_COLS;
        int c = e - r * OUT_COLS;
        int grow = (int)rowbase + r;
        int g = gsrc[r];
        float val;
        if (c < DD)               val = x[(size_t)grow * DD + c];
        else if (c < DD + 3)      val = pos[3 * grow + (c - DD)];
        else if (c < 2 * DD + 3)  val = x[(size_t)g * DD + (c - DD - 3)];
        else                      val = pos[3 * g + (c - 2 * DD - 3)];
        outp[e] = val;
    }
}

// ---------------- Kernel 3: optional batch output (if harness concatenates tuple) ----------
__global__ void batch_kernel(float* __restrict__ out) {
    int i = blockIdx.x * blockDim.x + threadIdx.x;
    if (i < BB * NN) {
        out[(size_t)BB * NN * OUT_COLS + (size_t)BB * NN * 3 + i] = (float)(i >> 12); // i / NN
    }
}

extern "C" void kernel_launch(void* const* d_in, const int* in_sizes, int n_in,
                              void* d_out, int out_size) {
    const float* x   = (const float*)d_in[0];
    const float* pos = (const float*)d_in[1];
    float* out = (float*)d_out;

    cudaFuncSetAttribute(fps_kernel, cudaFuncAttributeMaxDynamicSharedMemorySize,
                         (int)sizeof(FpsShared));
    fps_kernel<<<BB, FPS_THREADS, sizeof(FpsShared)>>>(pos);
    knn_out_kernel<<<dim3(NN / P2T, BB), P2T>>>(x, pos, out);

    const long long outx = (long long)BB * NN * OUT_COLS;            // 4390912
    const long long zs   = (long long)BB * NN * 3;                   // 98304
    if ((long long)out_size >= outx + zs) {
        cudaMemsetAsync(out + outx, 0, (size_t)zs * sizeof(float));
    }
    if ((long long)out_size >= outx + zs + (long long)BB * NN) {
        batch_kernel<<<(BB * NN + 255) / 256, 256>>>(out);
    }
}

// round 13
// speedup vs baseline: 1.0649x; 1.0131x over previous
#include <cuda_runtime.h>
#include <cstdint>
#include <cstddef>

#define BB 8
#define NN 4096
#define MM 1024
#define DD 64
#define PTS 16
#define NPAIR (PTS / 2)
#define FPS_THREADS 256   /* NN / PTS */
#define NWARP (FPS_THREADS / 32)
#define P2T 256
#define KNN_XBLOCKS (NN / P2T)   /* 16 */
#define TAILB 2
#define OUT_COLS 134      /* D + 3 + D + 3 */

// ---------------- scratch (no allocations allowed) ----------------
__device__ int   g_sidx[BB * MM];   // global index of sampled points
__device__ float g_lrx[BB * MM];    // sampled positions, SoA
__device__ float g_lry[BB * MM];
__device__ float g_lrz[BB * MM];

// ---------------- packed f32x2 helpers (bit-exact per-lane .rn ops) ------
__device__ __forceinline__ unsigned long long packf2(float lo, float hi) {
    unsigned long long r;
    asm("mov.b64 %0, {%1, %2};" : "=l"(r) : "f"(lo), "f"(hi));
    return r;
}
__device__ __forceinline__ void unpackf2(unsigned long long v, float& lo, float& hi) {
    asm("mov.b64 {%0, %1}, %2;" : "=f"(lo), "=f"(hi) : "l"(v));
}
__device__ __forceinline__ unsigned long long addx2(unsigned long long a, unsigned long long b) {
    unsigned long long r;
    asm("add.rn.f32x2 %0, %1, %2;" : "=l"(r) : "l"(a), "l"(b));
    return r;
}
__device__ __forceinline__ unsigned long long mulx2(unsigned long long a, unsigned long long b) {
    unsigned long long r;
    asm("mul.rn.f32x2 %0, %1, %2;" : "=l"(r) : "l"(a), "l"(b));
    return r;
}
__device__ __forceinline__ unsigned redux_max_u32(unsigned v) {
    unsigned r;
    asm("redux.sync.max.u32 %0, %1, 0xffffffff;" : "=r"(r) : "r"(v));
    return r;
}

struct FpsShared {
    unsigned long long wkey[2][NWARP];   // double-buffered per-warp keys
    float xs[NN], ys[NN], zs[NN];
};

// ---------------- Kernel 1: farthest point sampling, one CTA per cloud ----------------
// Byte-identical to the validated 377us / fps=336us configuration. Do not modify.
__global__ __launch_bounds__(FPS_THREADS, 1)
void fps_kernel(const float* __restrict__ pos) {
    extern __shared__ unsigned char smraw[];
    FpsShared* sm = reinterpret_cast<FpsShared*>(smraw);
    const int b = blockIdx.x;
    const int t = threadIdx.x;
    const int warp = t >> 5;
    const float* posb = pos + (size_t)b * NN * 3;

    for (int i = t; i < NN; i += FPS_THREADS) {
        sm->xs[i] = posb[3 * i + 0];
        sm->ys[i] = posb[3 * i + 1];
        sm->zs[i] = posb[3 * i + 2];
    }
    __syncthreads();

    // Per-thread points, pre-negated and packed in pairs: npx[p] = (-x[2p], -x[2p+1])
    unsigned long long npx[NPAIR], npy[NPAIR], npz[NPAIR];
    float mind[PTS];
    const int base = t * PTS;
#pragma unroll
    for (int p = 0; p < NPAIR; p++) {
        npx[p] = packf2(-sm->xs[base + 2 * p], -sm->xs[base + 2 * p + 1]);
        npy[p] = packf2(-sm->ys[base + 2 * p], -sm->ys[base + 2 * p + 1]);
        npz[p] = packf2(-sm->zs[base + 2 * p], -sm->zs[base + 2 * p + 1]);
    }
#pragma unroll
    for (int j = 0; j < PTS; j++) mind[j] = 3.402823466e+38f;  // finfo(float32).max

    float lx = sm->xs[0], ly = sm->ys[0], lz = sm->zs[0];  // winner of step 0
    if (t == 0) {
        g_sidx[b * MM] = b * NN;
        g_lrx[b * MM] = lx; g_lry[b * MM] = ly; g_lrz[b * MM] = lz;
    }

    for (int step = 1; step < MM; ++step) {
        const unsigned long long lxx = packf2(lx, lx);
        const unsigned long long lyy = packf2(ly, ly);
        const unsigned long long lzz = packf2(lz, lz);

        // Distances via packed math: dx = lx + (-px) == lx - px ; square identical to (px-lx)^2.
#pragma unroll
        for (int p = 0; p < NPAIR; p++) {
            unsigned long long dx = addx2(lxx, npx[p]);
            unsigned long long dy = addx2(lyy, npy[p]);
            unsigned long long dz = addx2(lzz, npz[p]);
            unsigned long long s  = addx2(addx2(mulx2(dx, dx), mulx2(dy, dy)),
                                          mulx2(dz, dz));
            float d0, d1;
            unpackf2(s, d0, d1);
            mind[2 * p]     = fminf(mind[2 * p], d0);
            mind[2 * p + 1] = fminf(mind[2 * p + 1], d1);
        }

        // In-thread argmax tree; lower index wins ties (first-occurrence semantics).
        float v[PTS]; int id[PTS];
#pragma unroll
        for (int j = 0; j < PTS; j++) { v[j] = mind[j]; id[j] = base + j; }
#pragma unroll
        for (int s = 1; s < PTS; s <<= 1) {
#pragma unroll
            for (int j = 0; j < PTS; j += 2 * s) {
                bool keep = v[j] >= v[j + s];
                v[j]  = keep ? v[j]  : v[j + s];
                id[j] = keep ? id[j] : id[j + s];
            }
        }

        // Warp argmax via two redux: max value bits, then min index among maxima.
        // (nonnegative floats: bit order == numeric order)
        unsigned vb = __float_as_uint(v[0]);
        unsigned vmax = redux_max_u32(vb);
        unsigned cand = (vb == vmax) ? ~(unsigned)id[0] : 0u;
        unsigned imax = redux_max_u32(cand);           // = ~(min idx among max lanes)
        if ((t & 31) == 0)
            sm->wkey[step & 1][warp] =
                ((unsigned long long)vmax << 32) | (unsigned long long)imax;
        __syncthreads();

        // Every thread reduces the NWARP keys redundantly (no second barrier).
        const unsigned long long* wk = sm->wkey[step & 1];
        unsigned long long bk = wk[0];
#pragma unroll
        for (int w = 1; w < NWARP; w++) {
            unsigned long long k = wk[w];
            if (k > bk) bk = k;   // equal keys impossible (idx embedded)
        }
        unsigned widx = ~((unsigned)bk);
        lx = sm->xs[widx]; ly = sm->ys[widx]; lz = sm->zs[widx];  // broadcast LDS

        if (t == 0) {
            g_sidx[b * MM + step] = b * NN + (int)widx;
            g_lrx[b * MM + step] = lx;
            g_lry[b * MM + step] = ly;
            g_lrz[b * MM + step] = lz;
        }
    }
}

// ---------------- Kernel 2: 1-NN + fused output gather + tuple-tail blocks ----------------
__global__ __launch_bounds__(P2T)
void knn_out_kernel(const float* __restrict__ x, const float* __restrict__ pos,
                    float* __restrict__ out, long long out_size) {
    // Tail blocks (blockIdx.x >= KNN_XBLOCKS): write zeros + batch outputs if present.
    if (blockIdx.x >= KNN_XBLOCKS) {
        if (blockIdx.y != 0) return;
        const long long outx = (long long)BB * NN * OUT_COLS;   // 4390912
        const long long zs   = (long long)BB * NN * 3;          // 98304
        const int gt = (blockIdx.x - KNN_XBLOCKS) * P2T + threadIdx.x;
        if (out_size >= outx + zs) {
            float4* z4 = reinterpret_cast<float4*>(out + outx);
            for (int i = gt; i < (int)(zs / 4); i += TAILB * P2T)
                z4[i] = make_float4(0.f, 0.f, 0.f, 0.f);
        }
        if (out_size >= outx + zs + (long long)BB * NN) {
            for (int i = gt; i < BB * NN; i += TAILB * P2T)
                out[outx + zs + i] = (float)(i >> 12);  // i / NN
        }
        return;
    }

    __shared__ unsigned long long nlx[MM / 2], nly[MM / 2], nlz[MM / 2];
    __shared__ int gsrc[P2T];

    const int b = blockIdx.y;
    // Load sampled positions, negated + packed in pairs.
    const float2* fx = (const float2*)(g_lrx) + b * (MM / 2);
    const float2* fy = (const float2*)(g_lry) + b * (MM / 2);
    const float2* fz = (const float2*)(g_lrz) + b * (MM / 2);
    for (int i = threadIdx.x; i < MM / 2; i += P2T) {
        float2 a = fx[i]; nlx[i] = packf2(-a.x, -a.y);
        float2 c = fy[i]; nly[i] = packf2(-c.x, -c.y);
        float2 e = fz[i]; nlz[i] = packf2(-e.x, -e.y);
    }
    __syncthreads();

    const int rlocal = blockIdx.x * P2T + threadIdx.x;
    const int row = b * NN + rlocal;
    const float ax = pos[3 * row + 0];
    const float ay = pos[3 * row + 1];
    const float az = pos[3 * row + 2];
    const unsigned long long axx = packf2(ax, ax);
    const unsigned long long ayy = packf2(ay, ay);
    const unsigned long long azz = packf2(az, az);

    // 4 interleaved argmin chains (2 packed pairs per iteration).
    float bv0 = 3.4e+38f, bv1 = 3.4e+38f, bv2 = 3.4e+38f, bv3 = 3.4e+38f;
    int bi0 = 0, bi1 = 1, bi2 = 2, bi3 = 3;
    for (int j = 0; j < MM; j += 4) {
        int p = j >> 1;
        unsigned long long dxA = addx2(axx, nlx[p]);
        unsigned long long dyA = addx2(ayy, nly[p]);
        unsigned long long dzA = addx2(azz, nlz[p]);
        unsigned long long sA  = addx2(addx2(mulx2(dxA, dxA), mulx2(dyA, dyA)),
                                       mulx2(dzA, dzA));
        unsigned long long dxB = addx2(axx, nlx[p + 1]);
        unsigned long long dyB = addx2(ayy, nly[p + 1]);
        unsigned long long dzB = addx2(azz, nlz[p + 1]);
        unsigned long long sB  = addx2(addx2(mulx2(dxB, dxB), mulx2(dyB, dyB)),
                                       mulx2(dzB, dzB));
        float d0, d1, d2, d3;
        unpackf2(sA, d0, d1);
        unpackf2(sB, d2, d3);
        if (d0 < bv0) { bv0 = d0; bi0 = j + 0; }
        if (d1 < bv1) { bv1 = d1; bi1 = j + 1; }
        if (d2 < bv2) { bv2 = d2; bi2 = j + 2; }
        if (d3 < bv3) { bv3 = d3; bi3 = j + 3; }
    }
    // Combine with first-index tie-break (matches jnp.argmin).
    bool t1 = (bv1 < bv0) || (bv1 == bv0 && bi1 < bi0);
    float va = t1 ? bv1 : bv0;  int ia = t1 ? bi1 : bi0;
    bool t2 = (bv3 < bv2) || (bv3 == bv2 && bi3 < bi2);
    float vb = t2 ? bv3 : bv2;  int ib = t2 ? bi3 : bi2;
    bool t3 = (vb < va) || (vb == va && ib < ia);
    int bi = t3 ? ib : ia;

    gsrc[threadIdx.x] = g_sidx[b * MM + bi];
    __syncthreads();

    // Cooperative, fully-coalesced output write: rows [rowbase, rowbase+P2T)
    const long long rowbase = (long long)b * NN + (long long)blockIdx.x * P2T;
    float* outp = out + (size_t)rowbase * OUT_COLS;
    for (int e = threadIdx.x; e < P2T * OUT_COLS; e += P2T) {
        int r = e / OUT_COLS;
        int c = e - r * OUT_COLS;
        int grow = (int)rowbase + r;
        int g = gsrc[r];
        float val;
        if (c < DD)               val = x[(size_t)grow * DD + c];
        else if (c < DD + 3)      val = pos[3 * grow + (c - DD)];
        else if (c < 2 * DD + 3)  val = x[(size_t)g * DD + (c - DD - 3)];
        else                      val = pos[3 * g + (c - 2 * DD - 3)];
        outp[e] = val;
    }
}

extern "C" void kernel_launch(void* const* d_in, const int* in_sizes, int n_in,
                              void* d_out, int out_size) {
    const float* x   = (const float*)d_in[0];
    const float* pos = (const float*)d_in[1];
    float* out = (float*)d_out;

    cudaFuncSetAttribute(fps_kernel, cudaFuncAttributeMaxDynamicSharedMemorySize,
                         (int)sizeof(FpsShared));
    fps_kernel<<<BB, FPS_THREADS, sizeof(FpsShared)>>>(pos);
    knn_out_kernel<<<dim3(KNN_XBLOCKS + TAILB, BB), P2T>>>(x, pos, out,
                                                           (long long)out_size);
}